// round 16
// baseline (speedup 1.0000x reference)
#include <cuda_runtime.h>
#include <cuda_fp16.h>
#include <cstdint>

// ---------------------------------------------------------------------------
// Problem constants
// ---------------------------------------------------------------------------
#define M_TOTAL 8192      // 4 * 2048
#define N_TOTAL 4096      // OUT_FEATURES
#define K_TOTAL 4096      // IN_FEATURES

__constant__ float c_codebook[16] = {
    0.0f,  0.0052f,  0.6667f,  1.0f,  0.3333f,  0.5f,  0.1667f,  0.25f,
    0.0f, -0.0052f, -0.6667f, -1.0f, -0.3333f, -0.5f, -0.1667f, -0.25f
};

// fp16 operand buffers, K-permuted (device globals: no runtime alloc).
// Within each 32-half K-group, positions 8t..8t+7 (t=0..3) hold original
// k = {2t,2t+1, 2t+8,2t+9, 16+2t,16+2t+1, 24+2t,24+2t+1}: thread tig=t reads
// one LDS.128 covering BOTH m16n8k16 k-steps of the 32-wide tile.
__device__ __align__(256) __half g_W[(size_t)N_TOTAL * K_TOTAL];   // 32 MB
__device__ __align__(256) __half g_X[(size_t)M_TOTAL * K_TOTAL];   // 64 MB

__device__ __forceinline__ uint32_t h2u(float a, float b) {
    __half2 h = __floats2half2_rn(a, b);   // .x = a (lower address)
    return *reinterpret_cast<uint32_t*>(&h);
}

// ---------------------------------------------------------------------------
// Dequant + permute: one thread -> one 32-element K-group of W (16 wp ints).
// LUT lives in SHARED memory: divergent-index loads broadcast instead of the
// 16-way LDC replay that bound the previous version.
// ---------------------------------------------------------------------------
__global__ void dequant_permute_kernel(const int* __restrict__ wp,
                                       const float* __restrict__ scale) {
    __shared__ float s_lut[16];
    if (threadIdx.x < 16) s_lut[threadIdx.x] = c_codebook[threadIdx.x];
    __syncthreads();

    const int g = blockIdx.x * blockDim.x + threadIdx.x;
    if (g >= (N_TOTAL * K_TOTAL) / 32) return;
    const int4* wp4 = reinterpret_cast<const int4*>(wp) + 4 * (size_t)g;
    int4 p0 = wp4[0], p1 = wp4[1], p2 = wp4[2], p3 = wp4[3];
    int b[16] = {p0.x, p0.y, p0.z, p0.w, p1.x, p1.y, p1.z, p1.w,
                 p2.x, p2.y, p2.z, p2.w, p3.x, p3.y, p3.z, p3.w};
    const float s = scale[g >> 1];

    uint32_t h2b[16];
#pragma unroll
    for (int j = 0; j < 16; j++)
        h2b[j] = h2u(s_lut[(b[j] >> 4) & 15] * s, s_lut[b[j] & 15] * s);

    uint4* o = reinterpret_cast<uint4*>(g_W + (size_t)g * 32);
#pragma unroll
    for (int t = 0; t < 4; t++)
        o[t] = make_uint4(h2b[t], h2b[t + 4], h2b[t + 8], h2b[t + 12]);
}

// ---------------------------------------------------------------------------
// Permute + fp16-convert x: one thread -> one 32-float K-group.
// ---------------------------------------------------------------------------
__global__ void permute_x_kernel(const float* __restrict__ x) {
    const int g = blockIdx.x * blockDim.x + threadIdx.x;
    if (g >= (M_TOTAL * K_TOTAL) / 32) return;
    const float4* in = reinterpret_cast<const float4*>(x + (size_t)g * 32);
    float v[32];
#pragma unroll
    for (int q = 0; q < 8; q++) {
        float4 f = in[q];
        v[4 * q] = f.x; v[4 * q + 1] = f.y; v[4 * q + 2] = f.z; v[4 * q + 3] = f.w;
    }
    uint4* o = reinterpret_cast<uint4*>(g_X + (size_t)g * 32);
#pragma unroll
    for (int t = 0; t < 4; t++)
        o[t] = make_uint4(h2u(v[2 * t],      v[2 * t + 1]),
                          h2u(v[2 * t + 8],  v[2 * t + 9]),
                          h2u(v[2 * t + 16], v[2 * t + 17]),
                          h2u(v[2 * t + 24], v[2 * t + 25]));
}

// ---------------------------------------------------------------------------
// GEMM: C[M,N] = X[M,K] * W[N,K]^T + bias   (fp16 operands, fp32 accum)
// CTA tile 256(M) x 128(N) x 32(K), 256 threads = 8 warps (4m x 2n),
// warp tile 64x64. 5-stage cp.async pipeline, 24KB/stage.
// LDS:tensor cycle ratio 0.69 -> tensor pipe is the binding resource.
// ---------------------------------------------------------------------------
#define BM 256
#define BN 128
#define BK 32                       // halves per k-tile (2 mma k-steps)
#define STAGES 5
#define ROW_BYTES 64                // BK * 2
#define A_STAGE_BYTES (BM * ROW_BYTES)    // 16384
#define B_STAGE_BYTES (BN * ROW_BYTES)    // 8192
#define STAGE_BYTES (A_STAGE_BYTES + B_STAGE_BYTES)   // 24576
#define NUM_KTILES (K_TOTAL / BK)         // 128

__device__ __forceinline__ uint32_t smem_u32(const void* p) {
    uint32_t a;
    asm("{ .reg .u64 t; cvta.to.shared.u64 t, %1; cvt.u32.u64 %0, t; }" : "=r"(a) : "l"(p));
    return a;
}
__device__ __forceinline__ void cp16(uint32_t dst, const void* src) {
    asm volatile("cp.async.cg.shared.global [%0], [%1], 16;" :: "r"(dst), "l"(src));
}
__device__ __forceinline__ void cp_commit() { asm volatile("cp.async.commit_group;"); }
template <int N>
__device__ __forceinline__ void cp_wait() { asm volatile("cp.async.wait_group %0;" :: "n"(N)); }

__device__ __forceinline__ void mma_f16(float c[4], uint32_t a0, uint32_t a1,
                                        uint32_t a2, uint32_t a3,
                                        uint32_t b0, uint32_t b1) {
    asm volatile(
        "mma.sync.aligned.m16n8k16.row.col.f32.f16.f16.f32 "
        "{%0,%1,%2,%3}, {%4,%5,%6,%7}, {%8,%9}, {%0,%1,%2,%3};\n"
        : "+f"(c[0]), "+f"(c[1]), "+f"(c[2]), "+f"(c[3])
        : "r"(a0), "r"(a1), "r"(a2), "r"(a3), "r"(b0), "r"(b1));
}

__global__ void __launch_bounds__(256, 1)
gemm_f16_kernel(const float* __restrict__ bias, float* __restrict__ C)
{
    extern __shared__ __align__(16) char smem[];   // STAGES * STAGE_BYTES
    __shared__ float s_bias[BN];

    const int tid  = threadIdx.x;
    const int lane = tid & 31;
    const int wid  = tid >> 5;
    const int warp_m = wid >> 1;   // 0..3
    const int warp_n = wid & 1;    // 0..1
    const int gid = lane >> 2;     // 0..7
    const int tig = lane & 3;      // 0..3

    // Block swizzle: chunks of 4 m-tiles x 32 n-tiles (128 CTAs, ~40MB L2 set)
    const int bid   = blockIdx.x;
    const int chunk = bid >> 7;            // 0..7
    const int rres  = bid & 127;
    const int bm    = chunk * 4 + (rres & 3);   // 0..31
    const int bn    = rres >> 2;                // 0..31

    const __half* Ag = g_X + (size_t)bm * BM * K_TOTAL;
    const __half* Bg = g_W + (size_t)bn * BN * K_TOTAL;

    if (tid < BN) s_bias[tid] = bias[bn * BN + tid];

    // Copy addressing: A 1024 chunks (256 rows x 4 segs), B 512 chunks.
    // Thread t: A rows r0,+64,+128,+192; B rows r0,+64; seg = 16B chunk.
    const int r0  = tid >> 2;       // 0..63
    const int seg = tid & 3;        // 0..3
    const uint32_t smem_base = smem_u32(smem);
    const uint32_t s_off = (uint32_t)(r0 * ROW_BYTES + seg * 16);  // bytes

    auto issue_tile = [&](int slot, int kt) {
        const uint32_t st = smem_base + (uint32_t)slot * STAGE_BYTES;
        const __half* a = Ag + (size_t)kt * BK + (size_t)r0 * K_TOTAL + seg * 8;
        const __half* b = Bg + (size_t)kt * BK + (size_t)r0 * K_TOTAL + seg * 8;
        cp16(st + s_off,                   a);
        cp16(st + s_off +  64 * ROW_BYTES, a + (size_t)64  * K_TOTAL);
        cp16(st + s_off + 128 * ROW_BYTES, a + (size_t)128 * K_TOTAL);
        cp16(st + s_off + 192 * ROW_BYTES, a + (size_t)192 * K_TOTAL);
        cp16(st + s_off + A_STAGE_BYTES,                   b);
        cp16(st + s_off + A_STAGE_BYTES + 64 * ROW_BYTES,  b + (size_t)64 * K_TOTAL);
    };

    float acc[4][8][4];
#pragma unroll
    for (int mi = 0; mi < 4; mi++)
#pragma unroll
        for (int ni = 0; ni < 8; ni++)
#pragma unroll
            for (int i = 0; i < 4; i++) acc[mi][ni][i] = 0.0f;

#pragma unroll
    for (int s = 0; s < STAGES - 1; s++) { issue_tile(s, s); cp_commit(); }

    const int arow = warp_m * 64 + gid;
    const int brow = warp_n * 64 + gid;

    for (int kt = 0; kt < NUM_KTILES; kt++) {
        cp_wait<STAGES - 2>();
        __syncthreads();

        if (kt + STAGES - 1 < NUM_KTILES) issue_tile((kt + STAGES - 1) % STAGES, kt + STAGES - 1);
        cp_commit();

        const char* Asb = smem + (kt % STAGES) * STAGE_BYTES;
        const char* Bsb = Asb + A_STAGE_BYTES;

        // A fragments first (32 regs live), then stream B per ni.
        uint4 alo[4], ahi[4];
#pragma unroll
        for (int mi = 0; mi < 4; mi++) {
            alo[mi] = *reinterpret_cast<const uint4*>(
                Asb + (arow + mi * 16) * ROW_BYTES + tig * 16);
            ahi[mi] = *reinterpret_cast<const uint4*>(
                Asb + (arow + mi * 16 + 8) * ROW_BYTES + tig * 16);
        }
#pragma unroll
        for (int ni = 0; ni < 8; ni++) {
            const uint4 bf = *reinterpret_cast<const uint4*>(
                Bsb + (brow + ni * 8) * ROW_BYTES + tig * 16);
#pragma unroll
            for (int mi = 0; mi < 4; mi++) {
                // k-step 0 (k 0..15): pairs .x/.y ; k-step 1 (k 16..31): .z/.w
                mma_f16(acc[mi][ni], alo[mi].x, ahi[mi].x, alo[mi].y, ahi[mi].y, bf.x, bf.y);
                mma_f16(acc[mi][ni], alo[mi].z, ahi[mi].z, alo[mi].w, ahi[mi].w, bf.z, bf.w);
            }
        }
    }

    // Epilogue: C = acc + bias
    const int m_base = bm * BM + warp_m * 64;
    const int n_base = bn * BN + warp_n * 64;
#pragma unroll
    for (int mi = 0; mi < 4; mi++) {
#pragma unroll
        for (int ni = 0; ni < 8; ni++) {
            const int r = m_base + mi * 16 + gid;
            const int c = n_base + ni * 8 + tig * 2;
            const float b0 = s_bias[c - bn * BN];
            const float b1 = s_bias[c - bn * BN + 1];
            float2 v0 = make_float2(acc[mi][ni][0] + b0, acc[mi][ni][1] + b1);
            float2 v1 = make_float2(acc[mi][ni][2] + b0, acc[mi][ni][3] + b1);
            *reinterpret_cast<float2*>(C + (size_t)r * N_TOTAL + c)       = v0;
            *reinterpret_cast<float2*>(C + (size_t)(r + 8) * N_TOTAL + c) = v1;
        }
    }
}

// ---------------------------------------------------------------------------
// Launch
// ---------------------------------------------------------------------------
extern "C" void kernel_launch(void* const* d_in, const int* in_sizes, int n_in,
                              void* d_out, int out_size) {
    const float* x     = (const float*)d_in[0];   // [4,2048,4096]
    const int*   wp    = (const int*)d_in[1];     // packed bytes as int32
    const float* scale = (const float*)d_in[2];
    const float* bias  = (const float*)d_in[3];
    float*       out   = (float*)d_out;

    const int w_groups = (N_TOTAL * K_TOTAL) / 32;   // 524288
    const int x_groups = (M_TOTAL * K_TOTAL) / 32;   // 1048576
    dequant_permute_kernel<<<w_groups / 256, 256>>>(wp, scale);
    permute_x_kernel<<<x_groups / 256, 256>>>(x);

    static const int smem_bytes = STAGES * STAGE_BYTES;   // 120 KB
    cudaFuncSetAttribute(gemm_f16_kernel,
                         cudaFuncAttributeMaxDynamicSharedMemorySize, smem_bytes);
    const int grid = (M_TOTAL / BM) * (N_TOTAL / BN);   // 1024
    gemm_f16_kernel<<<grid, 256, smem_bytes>>>(bias, out);
}

// round 17
// speedup vs baseline: 1.0068x; 1.0068x over previous
#include <cuda_runtime.h>
#include <cuda_fp16.h>
#include <cstdint>

// ---------------------------------------------------------------------------
// Problem constants
// ---------------------------------------------------------------------------
#define M_TOTAL 8192      // 4 * 2048
#define N_TOTAL 4096      // OUT_FEATURES
#define K_TOTAL 4096      // IN_FEATURES

__constant__ float c_codebook[16] = {
    0.0f,  0.0052f,  0.6667f,  1.0f,  0.3333f,  0.5f,  0.1667f,  0.25f,
    0.0f, -0.0052f, -0.6667f, -1.0f, -0.3333f, -0.5f, -0.1667f, -0.25f
};

// fp16 operand buffers, K-permuted (device globals: no runtime alloc).
// Within each 32-half K-group, positions 8t..8t+7 (t=0..3) hold original
// k = {2t,2t+1, 2t+8,2t+9, 16+2t,16+2t+1, 24+2t,24+2t+1}: thread tig=t reads
// one LDS.128 covering BOTH m16n8k16 k-steps of the 32-wide tile.
__device__ __align__(256) __half g_W[(size_t)N_TOTAL * K_TOTAL];   // 32 MB
__device__ __align__(256) __half g_X[(size_t)M_TOTAL * K_TOTAL];   // 64 MB

__device__ __forceinline__ uint32_t h2u(float a, float b) {
    __half2 h = __floats2half2_rn(a, b);   // .x = a (lower address)
    return *reinterpret_cast<uint32_t*>(&h);
}

// ---------------------------------------------------------------------------
// Dequant + permute (shared-memory LUT: broadcast, no LDC replay). 14 us.
// ---------------------------------------------------------------------------
__global__ void dequant_permute_kernel(const int* __restrict__ wp,
                                       const float* __restrict__ scale) {
    __shared__ float s_lut[16];
    if (threadIdx.x < 16) s_lut[threadIdx.x] = c_codebook[threadIdx.x];
    __syncthreads();

    const int g = blockIdx.x * blockDim.x + threadIdx.x;
    if (g >= (N_TOTAL * K_TOTAL) / 32) return;
    const int4* wp4 = reinterpret_cast<const int4*>(wp) + 4 * (size_t)g;
    int4 p0 = wp4[0], p1 = wp4[1], p2 = wp4[2], p3 = wp4[3];
    int b[16] = {p0.x, p0.y, p0.z, p0.w, p1.x, p1.y, p1.z, p1.w,
                 p2.x, p2.y, p2.z, p2.w, p3.x, p3.y, p3.z, p3.w};
    const float s = scale[g >> 1];

    uint32_t h2b[16];
#pragma unroll
    for (int j = 0; j < 16; j++)
        h2b[j] = h2u(s_lut[(b[j] >> 4) & 15] * s, s_lut[b[j] & 15] * s);

    uint4* o = reinterpret_cast<uint4*>(g_W + (size_t)g * 32);
#pragma unroll
    for (int t = 0; t < 4; t++)
        o[t] = make_uint4(h2b[t], h2b[t + 4], h2b[t + 8], h2b[t + 12]);
}

// ---------------------------------------------------------------------------
// Permute + fp16-convert x: one thread -> one 32-float K-group.
// ---------------------------------------------------------------------------
__global__ void permute_x_kernel(const float* __restrict__ x) {
    const int g = blockIdx.x * blockDim.x + threadIdx.x;
    if (g >= (M_TOTAL * K_TOTAL) / 32) return;
    const float4* in = reinterpret_cast<const float4*>(x + (size_t)g * 32);
    float v[32];
#pragma unroll
    for (int q = 0; q < 8; q++) {
        float4 f = in[q];
        v[4 * q] = f.x; v[4 * q + 1] = f.y; v[4 * q + 2] = f.z; v[4 * q + 3] = f.w;
    }
    uint4* o = reinterpret_cast<uint4*>(g_X + (size_t)g * 32);
#pragma unroll
    for (int t = 0; t < 4; t++)
        o[t] = make_uint4(h2u(v[2 * t],      v[2 * t + 1]),
                          h2u(v[2 * t + 8],  v[2 * t + 9]),
                          h2u(v[2 * t + 16], v[2 * t + 17]),
                          h2u(v[2 * t + 24], v[2 * t + 25]));
}

// ---------------------------------------------------------------------------
// GEMM: C[M,N] = X[M,K] * W[N,K]^T + bias   (fp16 operands, fp32 accum)
// Block 128x128 x BK32, 256 threads = 8 warps (2m x 4n), warp tile 64x32.
// 5-stage cp.async pipeline, 16KB/stage, 2 CTAs/SM (16 warps).
// mma nest ordered ks -> ni -> mi: same-acc reuse distance = 16 HMMAs.
// ---------------------------------------------------------------------------
#define BM 128
#define BN 128
#define BK 32                       // halves per k-tile (2 mma k-steps)
#define STAGES 5
#define ROW_BYTES 64                // BK * 2
#define A_STAGE_BYTES (BM * ROW_BYTES)    // 8192
#define STAGE_BYTES (2 * A_STAGE_BYTES)   // 16384
#define NUM_KTILES (K_TOTAL / BK)         // 128

__device__ __forceinline__ uint32_t smem_u32(const void* p) {
    uint32_t a;
    asm("{ .reg .u64 t; cvta.to.shared.u64 t, %1; cvt.u32.u64 %0, t; }" : "=r"(a) : "l"(p));
    return a;
}
__device__ __forceinline__ void cp16(uint32_t dst, const void* src) {
    asm volatile("cp.async.cg.shared.global [%0], [%1], 16;" :: "r"(dst), "l"(src));
}
__device__ __forceinline__ void cp_commit() { asm volatile("cp.async.commit_group;"); }
template <int N>
__device__ __forceinline__ void cp_wait() { asm volatile("cp.async.wait_group %0;" :: "n"(N)); }

__device__ __forceinline__ void mma_f16(float c[4], uint32_t a0, uint32_t a1,
                                        uint32_t a2, uint32_t a3,
                                        uint32_t b0, uint32_t b1) {
    asm volatile(
        "mma.sync.aligned.m16n8k16.row.col.f32.f16.f16.f32 "
        "{%0,%1,%2,%3}, {%4,%5,%6,%7}, {%8,%9}, {%0,%1,%2,%3};\n"
        : "+f"(c[0]), "+f"(c[1]), "+f"(c[2]), "+f"(c[3])
        : "r"(a0), "r"(a1), "r"(a2), "r"(a3), "r"(b0), "r"(b1));
}

__global__ void __launch_bounds__(256, 2)
gemm_f16_kernel(const float* __restrict__ bias, float* __restrict__ C)
{
    extern __shared__ __align__(16) char smem[];   // STAGES * STAGE_BYTES
    __shared__ float s_bias[BN];

    const int tid  = threadIdx.x;
    const int lane = tid & 31;
    const int wid  = tid >> 5;
    const int warp_m = wid & 1;
    const int warp_n = wid >> 1;
    const int gid = lane >> 2;
    const int tig = lane & 3;

    // Block swizzle: chunks of 8 m-tiles x 32 n-tiles (L2-friendly waves)
    const int bid   = blockIdx.x;
    const int chunk = bid >> 8;
    const int rres  = bid & 255;
    const int bm    = chunk * 8 + (rres & 7);   // 0..63
    const int bn    = rres >> 3;                // 0..31

    const __half* Ag = g_X + (size_t)bm * BM * K_TOTAL;
    const __half* Bg = g_W + (size_t)bn * BN * K_TOTAL;

    if (tid < BN) s_bias[tid] = bias[bn * BN + tid];

    // Copy addressing: 512 x 16B chunks per operand per tile.
    const int r0  = tid >> 2;       // 0..63
    const int seg = tid & 3;        // 0..3
    const uint32_t smem_base = smem_u32(smem);
    const size_t g_off0 = (size_t)r0 * K_TOTAL + seg * 8;          // halves
    const size_t g_off1 = (size_t)(r0 + 64) * K_TOTAL + seg * 8;
    const uint32_t s_off = (uint32_t)(r0 * ROW_BYTES + seg * 16);  // bytes

    auto issue_tile = [&](int slot, int kt) {
        const uint32_t st = smem_base + (uint32_t)slot * STAGE_BYTES;
        const __half* a = Ag + (size_t)kt * BK;
        const __half* b = Bg + (size_t)kt * BK;
        cp16(st + s_off,                              a + g_off0);
        cp16(st + s_off + 64 * ROW_BYTES,             a + g_off1);
        cp16(st + s_off + A_STAGE_BYTES,              b + g_off0);
        cp16(st + s_off + A_STAGE_BYTES + 64 * ROW_BYTES, b + g_off1);
    };

    float acc[4][4][4];
#pragma unroll
    for (int mi = 0; mi < 4; mi++)
#pragma unroll
        for (int ni = 0; ni < 4; ni++)
#pragma unroll
            for (int i = 0; i < 4; i++) acc[mi][ni][i] = 0.0f;

#pragma unroll
    for (int s = 0; s < STAGES - 1; s++) { issue_tile(s, s); cp_commit(); }

    const int arow = warp_m * 64 + gid;
    const int brow = warp_n * 32 + gid;

    for (int kt = 0; kt < NUM_KTILES; kt++) {
        cp_wait<STAGES - 2>();
        __syncthreads();

        if (kt + STAGES - 1 < NUM_KTILES) issue_tile((kt + STAGES - 1) % STAGES, kt + STAGES - 1);
        cp_commit();

        const char* Asb = smem + (kt % STAGES) * STAGE_BYTES;
        const char* Bsb = Asb + A_STAGE_BYTES;

        uint4 alo[4], ahi[4], bfr[4];
#pragma unroll
        for (int mi = 0; mi < 4; mi++) {
            alo[mi] = *reinterpret_cast<const uint4*>(
                Asb + (arow + mi * 16) * ROW_BYTES + tig * 16);
            ahi[mi] = *reinterpret_cast<const uint4*>(
                Asb + (arow + mi * 16 + 8) * ROW_BYTES + tig * 16);
        }
#pragma unroll
        for (int ni = 0; ni < 4; ni++)
            bfr[ni] = *reinterpret_cast<const uint4*>(
                Bsb + (brow + ni * 8) * ROW_BYTES + tig * 16);

        // k-step 0 (k 0..15): pairs .x/.y — 16 independent HMMAs
#pragma unroll
        for (int ni = 0; ni < 4; ni++)
#pragma unroll
            for (int mi = 0; mi < 4; mi++)
                mma_f16(acc[mi][ni], alo[mi].x, ahi[mi].x, alo[mi].y, ahi[mi].y,
                        bfr[ni].x, bfr[ni].y);
        // k-step 1 (k 16..31): pairs .z/.w — acc reuse distance = 16 HMMAs
#pragma unroll
        for (int ni = 0; ni < 4; ni++)
#pragma unroll
            for (int mi = 0; mi < 4; mi++)
                mma_f16(acc[mi][ni], alo[mi].z, ahi[mi].z, alo[mi].w, ahi[mi].w,
                        bfr[ni].z, bfr[ni].w);
    }

    // Epilogue: C = acc + bias
    const int m_base = bm * BM + warp_m * 64;
    const int n_base = bn * BN + warp_n * 32;
#pragma unroll
    for (int mi = 0; mi < 4; mi++) {
#pragma unroll
        for (int ni = 0; ni < 4; ni++) {
            const int r = m_base + mi * 16 + gid;
            const int c = n_base + ni * 8 + tig * 2;
            const float b0 = s_bias[c - bn * BN];
            const float b1 = s_bias[c - bn * BN + 1];
            float2 v0 = make_float2(acc[mi][ni][0] + b0, acc[mi][ni][1] + b1);
            float2 v1 = make_float2(acc[mi][ni][2] + b0, acc[mi][ni][3] + b1);
            *reinterpret_cast<float2*>(C + (size_t)r * N_TOTAL + c)       = v0;
            *reinterpret_cast<float2*>(C + (size_t)(r + 8) * N_TOTAL + c) = v1;
        }
    }
}

// ---------------------------------------------------------------------------
// Launch
// ---------------------------------------------------------------------------
extern "C" void kernel_launch(void* const* d_in, const int* in_sizes, int n_in,
                              void* d_out, int out_size) {
    const float* x     = (const float*)d_in[0];   // [4,2048,4096]
    const int*   wp    = (const int*)d_in[1];     // packed bytes as int32
    const float* scale = (const float*)d_in[2];
    const float* bias  = (const float*)d_in[3];
    float*       out   = (float*)d_out;

    const int w_groups = (N_TOTAL * K_TOTAL) / 32;   // 524288
    const int x_groups = (M_TOTAL * K_TOTAL) / 32;   // 1048576
    dequant_permute_kernel<<<w_groups / 256, 256>>>(wp, scale);
    permute_x_kernel<<<x_groups / 256, 256>>>(x);

    static const int smem_bytes = STAGES * STAGE_BYTES;   // 80 KB
    cudaFuncSetAttribute(gemm_f16_kernel,
                         cudaFuncAttributeMaxDynamicSharedMemorySize, smem_bytes);
    const int grid = (M_TOTAL / BM) * (N_TOTAL / BN);   // 2048
    gemm_f16_kernel<<<grid, 256, smem_bytes>>>(bias, out);
}